// round 1
// baseline (speedup 1.0000x reference)
#include <cuda_runtime.h>

// TBSyntaxParser: B=8192 states, buffer [B, L=128, H=50], W [3, 300], b [3],
// legal_actions [B,3], buffer_index [B] (int32), stack_indexes [B,3] (int32).
// out [B,3] float32 = exp(min(X@W.T + b, 10)) * legal_actions
// where X = concat(buffer[s, bi..bi+2, :], buffer[s, stk0..2, :]).

#define BB 8192
#define LL 128
#define HH 50
#define SIXH 300
#define WARPS_PER_CTA 8

__global__ __launch_bounds__(256, 8)
void tb_parser_kernel(const float* __restrict__ buffer,
                      const float* __restrict__ W,
                      const float* __restrict__ bvec,
                      const float* __restrict__ legal,
                      const int*   __restrict__ buf_idx,
                      const int*   __restrict__ stk_idx,
                      float*       __restrict__ out)
{
    __shared__ float Ws[3 * SIXH];

    const int tid = threadIdx.x;
    // Stage W into shared (903 floats ~ 3.6 KB); reused by 8 warps.
    #pragma unroll
    for (int i = tid; i < 3 * SIXH; i += 256) Ws[i] = W[i];
    __syncthreads();

    const int warp = tid >> 5;
    const int lane = tid & 31;
    const int state = blockIdx.x * WARPS_PER_CTA + warp;
    if (state >= BB) return;

    const int bi = buf_idx[state];
    const int s0 = stk_idx[state * 3 + 0];
    const int s1 = stk_idx[state * 3 + 1];
    const int s2 = stk_idx[state * 3 + 2];

    const float* base = buffer + (size_t)state * (LL * HH);

    float a0 = 0.f, a1 = 0.f, a2 = 0.f;

    // X[300] flattened: j -> (r = j/50, c = j%50); rows 0..2 = bi+r, 3..5 = stk.
    // Lanes stride by 32 => 10 iters (lanes 0..11) / 9 iters (lanes 12..31).
    #pragma unroll
    for (int j = lane; j < SIXH; j += 32) {
        const int r = j / HH;            // const-div -> IMAD.HI
        const int c = j - r * HH;
        const int row = (r == 0) ? bi
                      : (r == 1) ? bi + 1
                      : (r == 2) ? bi + 2
                      : (r == 3) ? s0
                      : (r == 4) ? s1 : s2;
        const float x = __ldg(base + row * HH + c);
        a0 = fmaf(x, Ws[j],            a0);
        a1 = fmaf(x, Ws[SIXH + j],     a1);
        a2 = fmaf(x, Ws[2 * SIXH + j], a2);
    }

    // Warp tree-reduce 3 accumulators.
    #pragma unroll
    for (int off = 16; off; off >>= 1) {
        a0 += __shfl_down_sync(0xffffffffu, a0, off);
        a1 += __shfl_down_sync(0xffffffffu, a1, off);
        a2 += __shfl_down_sync(0xffffffffu, a2, off);
    }

    if (lane == 0) {
        const float r0 = expf(fminf(a0 + bvec[0], 10.f)) * legal[state * 3 + 0];
        const float r1 = expf(fminf(a1 + bvec[1], 10.f)) * legal[state * 3 + 1];
        const float r2 = expf(fminf(a2 + bvec[2], 10.f)) * legal[state * 3 + 2];
        out[state * 3 + 0] = r0;
        out[state * 3 + 1] = r1;
        out[state * 3 + 2] = r2;
    }
}

extern "C" void kernel_launch(void* const* d_in, const int* in_sizes, int n_in,
                              void* d_out, int out_size)
{
    const float* buffer = (const float*)d_in[0];
    const float* W      = (const float*)d_in[1];
    const float* bvec   = (const float*)d_in[2];
    const float* legal  = (const float*)d_in[3];
    const int*   bufidx = (const int*)d_in[4];
    const int*   stkidx = (const int*)d_in[5];
    float* out = (float*)d_out;

    const int blocks = BB / WARPS_PER_CTA;  // 1024
    tb_parser_kernel<<<blocks, 256>>>(buffer, W, bvec, legal, bufidx, stkidx, out);
}